// round 8
// baseline (speedup 1.0000x reference)
#include <cuda_runtime.h>
#include <cuda_fp16.h>
#include <cstdint>

#define B_    16
#define C_    192
#define HW_   4096
#define NOUT  (C_*C_)
#define KSPLIT 8
#define KPER   (HW_/KSPLIT)     // 512
#define NKT    (KPER/64)        // 8 k-tiles (64 k each = one image row)

__device__ float g_sums[80];
__device__ int   g_cnt[80];

// ---------------------------------------------------------------------------
__device__ __forceinline__ uint32_t smem_u32(const void* p) {
    uint32_t a;
    asm("{ .reg .u64 t; cvta.to.shared.u64 t, %1; cvt.u32.u64 %0, t; }" : "=r"(a) : "l"(p));
    return a;
}
__device__ __forceinline__ void ldsm4(uint32_t* r, uint32_t addr) {
    asm volatile("ldmatrix.sync.aligned.m8n8.x4.shared.b16 {%0,%1,%2,%3}, [%4];"
                 : "=r"(r[0]), "=r"(r[1]), "=r"(r[2]), "=r"(r[3]) : "r"(addr));
}
__device__ __forceinline__ void mma16(float* d, const uint32_t* a, const uint32_t* b) {
    asm volatile("mma.sync.aligned.m16n8k16.row.col.f32.f16.f16.f32 "
                 "{%0,%1,%2,%3}, {%4,%5,%6,%7}, {%8,%9}, {%0,%1,%2,%3};"
                 : "+f"(d[0]), "+f"(d[1]), "+f"(d[2]), "+f"(d[3])
                 : "r"(a[0]), "r"(a[1]), "r"(a[2]), "r"(a[3]), "r"(b[0]), "r"(b[1]));
}
__device__ __forceinline__ uint32_t h2(float lo, float hi) {
    uint32_t r;
    asm("cvt.rn.f16x2.f32 %0, %1, %2;" : "=r"(r) : "f"(hi), "f"(lo));
    return r;
}
__device__ __forceinline__ void sts128(uint32_t addr, uint32_t a, uint32_t b,
                                       uint32_t c, uint32_t d) {
    asm volatile("st.shared.v4.b32 [%0], {%1,%2,%3,%4};"
                 :: "r"(addr), "r"(a), "r"(b), "r"(c), "r"(d) : "memory");
}

// ---------------------------------------------------------------------------
// GEMM: CTA tile M=96, N=192, K=512 (one split), fp16 HMMA m16n8k16.
// Fills read fp32 x directly (L2-resident) and convert to fp16 in-kernel:
//   - A (dx=0): 2 aligned LDG.128 + 4 cvt.f16x2 + 1 STS.128 per 16B chunk
//   - B (dx in {-1,0,1}): same + 1 clamped scalar LDG.32 for the edge element
// dy handled by clamped row pointer. No prep kernel, no fp16 scratch.
// smem/stage: A 96x128B + B 192x128B = 36864B, 2 stages.
// Epilogue: scalar atomicAdd into out[g] (overlaps across waves).
// ---------------------------------------------------------------------------
#define STAGE_B 36864
#define SM_REQ  (2 * STAGE_B)

__global__ __launch_bounds__(128, 2)
void cofe_mma(const float* __restrict__ x, float* __restrict__ out) {
    extern __shared__ char smraw[];
    const uint32_t smem = smem_u32(smraw);

    const int tid  = threadIdx.x;
    const int lane = tid & 31;
    const int wid  = tid >> 5;
    const int wr   = wid >> 1;
    const int wc   = wid & 1;

    const int bx  = blockIdx.x;
    const int s   = bx & 7;             // k-split
    const int mt  = (bx >> 3) & 1;      // M tile
    const int g   = bx >> 4;            // 0..79
    const int b   = g / 5, off = g % 5;
    const int dy  = (off < 3) ? -1 : 0;
    const int dx  = (off < 3) ? (off - 1) : ((off == 3) ? -1 : 0);

    const int cA0 = mt * 96;
    const int y0  = s * (KPER / 64);
    const float* xb = x + (size_t)b * C_ * HW_;
    const float* xA = xb + (size_t)cA0 * HW_;

    const int mrel  = (lane & 7) + ((lane >> 3) & 1) * 8;
    const int kcsA  = lane >> 4;
    const int nrel  = (lane & 7) + (lane >> 4) * 8;
    const int kcsB  = (lane >> 3) & 1;
    const int klane = lane & 7;

    float acc[3][12][4];
#pragma unroll
    for (int i = 0; i < 3; i++)
#pragma unroll
        for (int j = 0; j < 12; j++)
#pragma unroll
            for (int r = 0; r < 4; r++) acc[i][j][r] = 0.f;

    // ---- fills: fp32 source, convert to fp16 into swizzled smem ----
    auto fillA = [&](int st, int y) {
        uint32_t smA = smem + st * STAGE_B;
#pragma unroll
        for (int i = 0; i < 6; i++) {
            int q = tid + 128 * i;
            int m = q >> 3, t = q & 7;
            const float4* src = reinterpret_cast<const float4*>(
                xA + (size_t)m * HW_ + (y << 6)) + t * 2;
            float4 v1 = src[0], v2 = src[1];
            uint32_t dst = smA + m * 128 + ((t ^ (m & 7)) << 4);
            sts128(dst, h2(v1.x, v1.y), h2(v1.z, v1.w),
                        h2(v2.x, v2.y), h2(v2.z, v2.w));
        }
    };
    auto fillB = [&](int st, int y) {
        uint32_t smB = smem + st * STAGE_B + 12288;
        int py = y + dy; if (py < 0) py = 0;
#pragma unroll
        for (int i = 0; i < 12; i++) {
            int q = i * 128 + tid;
            int n = q >> 3, t = q & 7;
            const float* base = xb + (size_t)n * HW_ + (py << 6);
            const float4* s4 = reinterpret_cast<const float4*>(base) + t * 2;
            float4 v1 = s4[0], v2 = s4[1];
            uint32_t dst = smB + n * 128 + ((t ^ (n & 7)) << 4);
            if (dx == 0) {
                sts128(dst, h2(v1.x, v1.y), h2(v1.z, v1.w),
                            h2(v2.x, v2.y), h2(v2.z, v2.w));
            } else if (dx > 0) {
                int ei = t * 8 + 8; if (ei > 63) ei = 63;
                float e = __ldg(base + ei);
                sts128(dst, h2(v1.y, v1.z), h2(v1.w, v2.x),
                            h2(v2.y, v2.z), h2(v2.w, e));
            } else {
                int ei = t * 8 - 1; if (ei < 0) ei = 0;
                float e = __ldg(base + ei);
                sts128(dst, h2(e, v1.x), h2(v1.y, v1.z),
                            h2(v1.w, v2.x), h2(v2.y, v2.z));
            }
        }
    };

    // ---- prologue ----
    fillB(0, y0);
    fillA(0, y0);

    // ---- main loop ----
    for (int kt = 0; kt < NKT; kt++) {
        int st = kt & 1;
        __syncthreads();                 // fills visible / prev consume done
        if (kt + 1 < NKT) {
            fillB(st ^ 1, y0 + kt + 1);
            fillA(st ^ 1, y0 + kt + 1);
        }
        __syncthreads();                 // wait fill of CURRENT stage (kt==0)
                                         // and publish next-stage fills

        uint32_t smA = smem + st * STAGE_B;
        uint32_t smB = smA + 12288;
        uint32_t aA0 = smA + (wr * 48 + mrel) * 128;
        uint32_t aB0 = smB + (wc * 96 + nrel) * 128;

#pragma unroll
        for (int ks = 0; ks < 4; ks++) {
            uint32_t af[3][4], bf[6][4];
#pragma unroll
            for (int i = 0; i < 3; i++)
                ldsm4(af[i], aA0 + i * (16 * 128) + (((ks * 2 + kcsA) ^ klane) << 4));
#pragma unroll
            for (int t = 0; t < 6; t++)
                ldsm4(bf[t], aB0 + t * (16 * 128) + (((ks * 2 + kcsB) ^ klane) << 4));
#pragma unroll
            for (int i = 0; i < 3; i++)
#pragma unroll
                for (int j = 0; j < 12; j++)
                    mma16(acc[i][j], af[i], &bf[j >> 1][(j & 1) * 2]);
        }
    }

    // ---- epilogue: RED into out[g] ----
    float* po = out + (size_t)g * NOUT;
    const int rA = lane >> 2, cB = (lane & 3) * 2;
#pragma unroll
    for (int i = 0; i < 3; i++) {
        int c0 = cA0 + wr * 48 + i * 16 + rA;
#pragma unroll
        for (int j = 0; j < 12; j++) {
            int d0 = wc * 96 + j * 8 + cB;
            atomicAdd(po + (size_t)c0 * C_ + d0,     acc[i][j][0]);
            atomicAdd(po + (size_t)c0 * C_ + d0 + 1, acc[i][j][1]);
            atomicAdd(po + (size_t)(c0 + 8) * C_ + d0,     acc[i][j][2]);
            atomicAdd(po + (size_t)(c0 + 8) * C_ + d0 + 1, acc[i][j][3]);
        }
    }
}

// ---------------------------------------------------------------------------
// zero-init: out (80*36864 floats) + norm counters (needed per graph replay)
// ---------------------------------------------------------------------------
__global__ __launch_bounds__(1024) void cofe_zero(float* __restrict__ out) {
    int i = blockIdx.x * 1024 + threadIdx.x;              // 720 blocks exact
    reinterpret_cast<float4*>(out)[i] = make_float4(0.f, 0.f, 0.f, 0.f);
    if (blockIdx.x == 0 && threadIdx.x < 80) {
        g_sums[threadIdx.x] = 0.f;
        g_cnt[threadIdx.x]  = 0;
    }
}

// ---------------------------------------------------------------------------
// fused norm: 8 blocks per g (grid 640, all resident -> spin barrier safe).
// ---------------------------------------------------------------------------
__global__ __launch_bounds__(256) void cofe_norm(float* __restrict__ out) {
    const int g = blockIdx.x >> 3, seg = blockIdx.x & 7;
    float4* p = reinterpret_cast<float4*>(out + (size_t)g * NOUT + seg * 4608);
    const int tid = threadIdx.x;

    float ss = 0.f;
#pragma unroll
    for (int i = tid; i < 1152; i += 256) {
        float4 v = p[i];
        ss += v.x * v.x + v.y * v.y + v.z * v.z + v.w * v.w;
    }
    __shared__ float red[8];
    __shared__ float s_scale;
#pragma unroll
    for (int d = 16; d > 0; d >>= 1) ss += __shfl_xor_sync(0xffffffffu, ss, d);
    if ((tid & 31) == 0) red[tid >> 5] = ss;
    __syncthreads();
    if (tid == 0) {
        float v = red[0] + red[1] + red[2] + red[3] +
                  red[4] + red[5] + red[6] + red[7];
        atomicAdd(&g_sums[g], v);
        __threadfence();
        atomicAdd(&g_cnt[g], 1);
        while (atomicAdd(&g_cnt[g], 0) < 8) { }
        __threadfence();
        float tot = atomicAdd(&g_sums[g], 0.0f);
        s_scale = 1.0f / fmaxf(sqrtf(tot), 1e-12f);
    }
    __syncthreads();
    const float scale = s_scale;

#pragma unroll
    for (int i = tid; i < 1152; i += 256) {
        float4 v = p[i];
        v.x *= scale; v.y *= scale; v.z *= scale; v.w *= scale;
        p[i] = v;
    }
}

// ---------------------------------------------------------------------------
extern "C" void kernel_launch(void* const* d_in, const int* in_sizes, int n_in,
                              void* d_out, int out_size) {
    const float* x = (const float*)d_in[0];
    float* out = (float*)d_out;

    cofe_zero<<<720, 1024>>>(out);
    cudaFuncSetAttribute(cofe_mma, cudaFuncAttributeMaxDynamicSharedMemorySize, SM_REQ);
    cofe_mma<<<1280, 128, SM_REQ>>>(x, out);
    cofe_norm<<<640, 256>>>(out);
}

// round 9
// speedup vs baseline: 1.4948x; 1.4948x over previous
#include <cuda_runtime.h>
#include <cuda_fp16.h>
#include <cstdint>

#define B_    16
#define C_    192
#define HW_   4096
#define NOUT  (C_*C_)
#define KSPLIT 8
#define KPER   (HW_/KSPLIT)     // 512
#define NKT    (KPER/64)        // 8 k-tiles (64 k each = one image row)

__device__ float g_sums[80];
__device__ int   g_cnt[80];
// fp16 even variant: [bc][y][64]  (row-major, same layout as x)
__device__ __half g_even[(size_t)B_ * C_ * HW_];
// fp16 odd variant:  [bc*64+y][72]; row = [x0, x0, x1, ..., x63, x63] (66 used)
__device__ __half g_odd[(size_t)B_ * C_ * 64 * 72];

// ---------------------------------------------------------------------------
__device__ __forceinline__ uint32_t smem_u32(const void* p) {
    uint32_t a;
    asm("{ .reg .u64 t; cvta.to.shared.u64 t, %1; cvt.u32.u64 %0, t; }" : "=r"(a) : "l"(p));
    return a;
}
__device__ __forceinline__ void cp_async16(uint32_t dst, const void* src) {
    asm volatile("cp.async.cg.shared.global [%0], [%1], 16;" :: "r"(dst), "l"(src) : "memory");
}
__device__ __forceinline__ void cp_async4(uint32_t dst, const void* src) {
    asm volatile("cp.async.ca.shared.global [%0], [%1], 4;" :: "r"(dst), "l"(src) : "memory");
}
__device__ __forceinline__ void cp_commit() {
    asm volatile("cp.async.commit_group;" ::: "memory");
}
template <int N>
__device__ __forceinline__ void cp_wait() {
    asm volatile("cp.async.wait_group %0;" :: "n"(N) : "memory");
}
__device__ __forceinline__ void ldsm4(uint32_t* r, uint32_t addr) {
    asm volatile("ldmatrix.sync.aligned.m8n8.x4.shared.b16 {%0,%1,%2,%3}, [%4];"
                 : "=r"(r[0]), "=r"(r[1]), "=r"(r[2]), "=r"(r[3]) : "r"(addr));
}
__device__ __forceinline__ void mma16(float* d, const uint32_t* a, const uint32_t* b) {
    asm volatile("mma.sync.aligned.m16n8k16.row.col.f32.f16.f16.f32 "
                 "{%0,%1,%2,%3}, {%4,%5,%6,%7}, {%8,%9}, {%0,%1,%2,%3};"
                 : "+f"(d[0]), "+f"(d[1]), "+f"(d[2]), "+f"(d[3])
                 : "r"(a[0]), "r"(a[1]), "r"(a[2]), "r"(a[3]), "r"(b[0]), "r"(b[1]));
}
__device__ __forceinline__ uint32_t h2(float lo, float hi) {
    uint32_t r;
    asm("cvt.rn.f16x2.f32 %0, %1, %2;" : "=r"(r) : "f"(hi), "f"(lo));
    return r;
}

// ---------------------------------------------------------------------------
// prep (fused with output zero-init): build even + padded-odd fp16 variants.
// thread = (row r in [0,196608), j in [0,16)): handles 4 floats.
// ---------------------------------------------------------------------------
__global__ __launch_bounds__(256) void cofe_prep(const float* __restrict__ x,
                                                 float* __restrict__ out) {
    int idx = blockIdx.x * 256 + threadIdx.x;     // 12288*256 = 3,145,728
    if (idx < 737280)
        reinterpret_cast<float4*>(out)[idx] = make_float4(0.f, 0.f, 0.f, 0.f);
    if (idx < 80) { g_sums[idx] = 0.f; g_cnt[idx] = 0; }

    int r = idx >> 4;            // row = bc*64 + y
    int j = idx & 15;            // quad within row
    const float* src = x + (size_t)r * 64 + j * 4;
    float4 v = *reinterpret_cast<const float4*>(src);
    float prev = (j == 0) ? v.x : src[-1];

    // even: units 2j,2j+1 -> (x4j,x4j+1),(x4j+2,x4j+3)
    *reinterpret_cast<uint2*>(g_even + (size_t)r * 64 + j * 4) =
        make_uint2(h2(v.x, v.y), h2(v.z, v.w));
    // odd: units 2j,2j+1 -> (x[4j-1],x4j),(x4j+1,x4j+2)
    __half* orow = g_odd + (size_t)r * 72;
    *reinterpret_cast<uint2*>(orow + j * 4) =
        make_uint2(h2(prev, v.x), h2(v.y, v.z));
    if (j == 15)   // unit 32 -> (x63, x63)
        *reinterpret_cast<uint32_t*>(orow + 64) = h2(v.w, v.w);
}

// ---------------------------------------------------------------------------
// GEMM: CTA tile M=96, N=192, K=512 (one split), fp16 HMMA m16n8k16.
// 128 threads = 4 warps (2x2), warp tile 48x96, k-tile 64 (one image row).
// Fills (cp.async):
//   A:        g_even, 16B chunks
//   B dx= 0:  g_even, 16B chunks
//   B dx=-1:  g_odd bytes [16t..16t+15]  (16B aligned)
//   B dx=+1:  g_odd bytes [16t+4..16t+19] as 4x cp.async.4
// smem/stage: A 96x128B + B 192x128B = 36864B, 2 stages.
// Epilogue: scalar atomicAdd into out[g].
// ---------------------------------------------------------------------------
#define STAGE_B 36864
#define SM_REQ  (2 * STAGE_B)

__global__ __launch_bounds__(128, 2)
void cofe_mma(float* __restrict__ out) {
    extern __shared__ char smraw[];
    const uint32_t smem = smem_u32(smraw);

    const int tid  = threadIdx.x;
    const int lane = tid & 31;
    const int wid  = tid >> 5;
    const int wr   = wid >> 1;
    const int wc   = wid & 1;

    const int bx  = blockIdx.x;
    const int s   = bx & 7;             // k-split
    const int mt  = (bx >> 3) & 1;      // M tile
    const int g   = bx >> 4;            // 0..79
    const int b   = g / 5, off = g % 5;
    const int dy  = (off < 3) ? -1 : 0;
    const int dx  = (off < 3) ? (off - 1) : ((off == 3) ? -1 : 0);

    const int cA0 = mt * 96;
    const int y0  = s * (KPER / 64);
    const __half* xAh = g_even + (size_t)(b * C_ + cA0) * HW_;

    const int mrel  = (lane & 7) + ((lane >> 3) & 1) * 8;
    const int kcsA  = lane >> 4;
    const int nrel  = (lane & 7) + (lane >> 4) * 8;
    const int kcsB  = (lane >> 3) & 1;
    const int klane = lane & 7;

    float acc[3][12][4];
#pragma unroll
    for (int i = 0; i < 3; i++)
#pragma unroll
        for (int j = 0; j < 12; j++)
#pragma unroll
            for (int r = 0; r < 4; r++) acc[i][j][r] = 0.f;

    auto fillA = [&](int st, int y) {
        uint32_t smA = smem + st * STAGE_B;
#pragma unroll
        for (int i = 0; i < 6; i++) {
            int q = tid + 128 * i;
            int m = q >> 3, t = q & 7;
            uint32_t dst = smA + m * 128 + ((t ^ (m & 7)) << 4);
            cp_async16(dst, xAh + (size_t)m * HW_ + (y << 6) + t * 8);
        }
    };
    auto fillB = [&](int st, int y) {
        uint32_t smB = smem + st * STAGE_B + 12288;
        int py = y + dy; if (py < 0) py = 0;
#pragma unroll
        for (int i = 0; i < 12; i++) {
            int q = i * 128 + tid;
            int n = q >> 3, t = q & 7;
            uint32_t dst = smB + n * 128 + ((t ^ (n & 7)) << 4);
            if (dx == 0) {
                cp_async16(dst, g_even + (size_t)(b * C_ + n) * HW_ + (py << 6) + t * 8);
            } else {
                const __half* orow = g_odd + ((size_t)(b * C_ + n) * 64 + py) * 72;
                if (dx < 0) {
                    cp_async16(dst, orow + t * 8);            // bytes 16t..+15
                } else {
#pragma unroll
                    for (int e = 0; e < 4; e++)               // bytes 16t+4..+19
                        cp_async4(dst + e * 4, orow + t * 8 + 2 + e * 2);
                }
            }
        }
    };

    // ---- prologue ----
    fillB(0, y0);
    fillA(0, y0);
    cp_commit();

    // ---- main loop ----
    for (int kt = 0; kt < NKT; kt++) {
        int st = kt & 1;
        __syncthreads();
        if (kt + 1 < NKT) {
            fillB(st ^ 1, y0 + kt + 1);
            fillA(st ^ 1, y0 + kt + 1);
            cp_commit();
            cp_wait<1>();
        } else {
            cp_wait<0>();
        }
        __syncthreads();

        uint32_t smA = smem + st * STAGE_B;
        uint32_t smB = smA + 12288;
        uint32_t aA0 = smA + (wr * 48 + mrel) * 128;
        uint32_t aB0 = smB + (wc * 96 + nrel) * 128;

#pragma unroll
        for (int ks = 0; ks < 4; ks++) {
            uint32_t af[3][4], bf[6][4];
#pragma unroll
            for (int i = 0; i < 3; i++)
                ldsm4(af[i], aA0 + i * (16 * 128) + (((ks * 2 + kcsA) ^ klane) << 4));
#pragma unroll
            for (int t = 0; t < 6; t++)
                ldsm4(bf[t], aB0 + t * (16 * 128) + (((ks * 2 + kcsB) ^ klane) << 4));
#pragma unroll
            for (int i = 0; i < 3; i++)
#pragma unroll
                for (int j = 0; j < 12; j++)
                    mma16(acc[i][j], af[i], &bf[j >> 1][(j & 1) * 2]);
        }
    }

    // ---- epilogue: RED into out[g] ----
    float* po = out + (size_t)g * NOUT;
    const int rA = lane >> 2, cB = (lane & 3) * 2;
#pragma unroll
    for (int i = 0; i < 3; i++) {
        int c0 = cA0 + wr * 48 + i * 16 + rA;
#pragma unroll
        for (int j = 0; j < 12; j++) {
            int d0 = wc * 96 + j * 8 + cB;
            atomicAdd(po + (size_t)c0 * C_ + d0,     acc[i][j][0]);
            atomicAdd(po + (size_t)c0 * C_ + d0 + 1, acc[i][j][1]);
            atomicAdd(po + (size_t)(c0 + 8) * C_ + d0,     acc[i][j][2]);
            atomicAdd(po + (size_t)(c0 + 8) * C_ + d0 + 1, acc[i][j][3]);
        }
    }
}

// ---------------------------------------------------------------------------
// fused norm: 8 blocks per g (grid 640, all resident -> spin barrier safe).
// ---------------------------------------------------------------------------
__global__ __launch_bounds__(256) void cofe_norm(float* __restrict__ out) {
    const int g = blockIdx.x >> 3, seg = blockIdx.x & 7;
    float4* p = reinterpret_cast<float4*>(out + (size_t)g * NOUT + seg * 4608);
    const int tid = threadIdx.x;

    float ss = 0.f;
#pragma unroll
    for (int i = tid; i < 1152; i += 256) {
        float4 v = p[i];
        ss += v.x * v.x + v.y * v.y + v.z * v.z + v.w * v.w;
    }
    __shared__ float red[8];
    __shared__ float s_scale;
#pragma unroll
    for (int d = 16; d > 0; d >>= 1) ss += __shfl_xor_sync(0xffffffffu, ss, d);
    if ((tid & 31) == 0) red[tid >> 5] = ss;
    __syncthreads();
    if (tid == 0) {
        float v = red[0] + red[1] + red[2] + red[3] +
                  red[4] + red[5] + red[6] + red[7];
        atomicAdd(&g_sums[g], v);
        __threadfence();
        atomicAdd(&g_cnt[g], 1);
        while (atomicAdd(&g_cnt[g], 0) < 8) { }
        __threadfence();
        float tot = atomicAdd(&g_sums[g], 0.0f);
        s_scale = 1.0f / fmaxf(sqrtf(tot), 1e-12f);
    }
    __syncthreads();
    const float scale = s_scale;

#pragma unroll
    for (int i = tid; i < 1152; i += 256) {
        float4 v = p[i];
        v.x *= scale; v.y *= scale; v.z *= scale; v.w *= scale;
        p[i] = v;
    }
}

// ---------------------------------------------------------------------------
extern "C" void kernel_launch(void* const* d_in, const int* in_sizes, int n_in,
                              void* d_out, int out_size) {
    const float* x = (const float*)d_in[0];
    float* out = (float*)d_out;

    cofe_prep<<<12288, 256>>>(x, out);
    cudaFuncSetAttribute(cofe_mma, cudaFuncAttributeMaxDynamicSharedMemorySize, SM_REQ);
    cofe_mma<<<1280, 128, SM_REQ>>>(out);
    cofe_norm<<<640, 256>>>(out);
}

// round 10
// speedup vs baseline: 1.9755x; 1.3216x over previous
#include <cuda_runtime.h>
#include <cuda_fp16.h>
#include <cstdint>

#define B_    16
#define C_    192
#define HW_   4096
#define NOUT  (C_*C_)
#define NROWS 10240            // 160 positions x 64 image rows

__device__ float g_sums[80];
__device__ int   g_cnt[80];
// fp16 variants: v=0 -> dx=-1, v=1 -> dx=0, v=2 -> dx=+1 (edge-clamped)
__device__ __half g_xh[(size_t)3 * B_ * C_ * HW_];

// ---------------------------------------------------------------------------
__device__ __forceinline__ uint32_t smem_u32(const void* p) {
    uint32_t a;
    asm("{ .reg .u64 t; cvta.to.shared.u64 t, %1; cvt.u32.u64 %0, t; }" : "=r"(a) : "l"(p));
    return a;
}
__device__ __forceinline__ void cp_async16(uint32_t dst, const void* src) {
    asm volatile("cp.async.cg.shared.global [%0], [%1], 16;" :: "r"(dst), "l"(src) : "memory");
}
__device__ __forceinline__ void cp_commit() {
    asm volatile("cp.async.commit_group;" ::: "memory");
}
template <int N>
__device__ __forceinline__ void cp_wait() {
    asm volatile("cp.async.wait_group %0;" :: "n"(N) : "memory");
}
__device__ __forceinline__ void ldsm4(uint32_t* r, uint32_t addr) {
    asm volatile("ldmatrix.sync.aligned.m8n8.x4.shared.b16 {%0,%1,%2,%3}, [%4];"
                 : "=r"(r[0]), "=r"(r[1]), "=r"(r[2]), "=r"(r[3]) : "r"(addr));
}
__device__ __forceinline__ void mma16(float* d, const uint32_t* a, const uint32_t* b) {
    asm volatile("mma.sync.aligned.m16n8k16.row.col.f32.f16.f16.f32 "
                 "{%0,%1,%2,%3}, {%4,%5,%6,%7}, {%8,%9}, {%0,%1,%2,%3};"
                 : "+f"(d[0]), "+f"(d[1]), "+f"(d[2]), "+f"(d[3])
                 : "r"(a[0]), "r"(a[1]), "r"(a[2]), "r"(a[3]), "r"(b[0]), "r"(b[1]));
}

// ---------------------------------------------------------------------------
// prep (fused zero-init): fp16-convert x into 3 dx-shifted variants.
// ---------------------------------------------------------------------------
__global__ __launch_bounds__(256) void cofe_prep(const float* __restrict__ x,
                                                 float* __restrict__ out) {
    int idx = blockIdx.x * 256 + threadIdx.x;     // 12288 * 256
    if (idx < 737280)
        reinterpret_cast<float4*>(out)[idx] = make_float4(0.f, 0.f, 0.f, 0.f);
    if (idx < 80) { g_sums[idx] = 0.f; g_cnt[idx] = 0; }

    int row = idx >> 4;                            // (b*C + c)*64 + y
    int q   = idx & 15;
    const float* src = x + (size_t)row * 64 + q * 4;
    float4 v = *reinterpret_cast<const float4*>(src);
    float lm = (q == 0)  ? v.x : src[-1];
    float rp = (q == 15) ? v.w : src[4];

    size_t o = (size_t)row * 64 + q * 4;
    const size_t VS = (size_t)B_ * C_ * HW_;
    __half2* d0 = reinterpret_cast<__half2*>(g_xh + o);            // dx=-1
    __half2* d1 = reinterpret_cast<__half2*>(g_xh + VS + o);       // dx=0
    __half2* d2 = reinterpret_cast<__half2*>(g_xh + 2 * VS + o);   // dx=+1
    d0[0] = __floats2half2_rn(lm,  v.x); d0[1] = __floats2half2_rn(v.y, v.z);
    d1[0] = __floats2half2_rn(v.x, v.y); d1[1] = __floats2half2_rn(v.z, v.w);
    d2[0] = __floats2half2_rn(v.y, v.z); d2[1] = __floats2half2_rn(v.w, rp);
}

// ---------------------------------------------------------------------------
// Persistent GEMM: grid = 2*SMs (one wave). Work = NROWS rows; row rr:
//   pos = rr>>6 (g = pos>>1, mt = pos&1), y = rr&63.
// Per row: fill A(96x64) + B(192x64) fp16 via cp.async (double-buffered),
// 4x m16n8k16 k-steps, warp tile 48x96. Flush acc via atomics at position
// boundaries (<=2 per CTA).
// ---------------------------------------------------------------------------
#define STAGE_B 36864
#define SM_REQ  (2 * STAGE_B)

__global__ __launch_bounds__(128, 2)
void cofe_mma(float* __restrict__ out) {
    extern __shared__ char smraw[];
    const uint32_t smem = smem_u32(smraw);

    const int tid  = threadIdx.x;
    const int lane = tid & 31;
    const int wid  = tid >> 5;
    const int wr   = wid >> 1;
    const int wc   = wid & 1;

    const int G  = gridDim.x;
    const int r0 = (int)(((long long)blockIdx.x * NROWS) / G);
    const int r1 = (int)(((long long)(blockIdx.x + 1) * NROWS) / G);

    const size_t VS = (size_t)B_ * C_ * HW_;

    const int mrel  = (lane & 7) + ((lane >> 3) & 1) * 8;
    const int kcsA  = lane >> 4;
    const int nrel  = (lane & 7) + (lane >> 4) * 8;
    const int kcsB  = (lane >> 3) & 1;
    const int klane = lane & 7;

    float acc[3][12][4];
#pragma unroll
    for (int i = 0; i < 3; i++)
#pragma unroll
        for (int j = 0; j < 12; j++)
#pragma unroll
            for (int r = 0; r < 4; r++) acc[i][j][r] = 0.f;

    // ---- fills parameterized by global row index ----
    auto fillA = [&](int st, int rr) {
        int pos = rr >> 6, y = rr & 63;
        int gg  = pos >> 1, mtv = pos & 1;
        int bb  = gg / 5;
        const __half* xAh = g_xh + VS + ((size_t)(bb * C_ + mtv * 96)) * HW_;
        uint32_t smA = smem + st * STAGE_B;
#pragma unroll
        for (int i = 0; i < 6; i++) {
            int q = tid + 128 * i;
            int m = q >> 3, t = q & 7;
            uint32_t dst = smA + m * 128 + ((t ^ (m & 7)) << 4);
            cp_async16(dst, xAh + (size_t)m * HW_ + (y << 6) + t * 8);
        }
    };
    auto fillB = [&](int st, int rr) {
        int pos = rr >> 6, y = rr & 63;
        int gg  = pos >> 1;
        int bb  = gg / 5, off = gg % 5;
        int dyv = (off < 3) ? -1 : 0;
        int dxv = (off < 3) ? (off - 1) : ((off == 3) ? -1 : 0);
        int py  = y + dyv; if (py < 0) py = 0;
        const __half* xBh = g_xh + (size_t)(dxv + 1) * VS + (size_t)(bb * C_) * HW_;
        uint32_t smB = smem + st * STAGE_B + 12288;
#pragma unroll
        for (int i = 0; i < 12; i++) {
            int q = i * 128 + tid;
            int n = q >> 3, t = q & 7;
            uint32_t dst = smB + n * 128 + ((t ^ (n & 7)) << 4);
            cp_async16(dst, xBh + (size_t)n * HW_ + (py << 6) + t * 8);
        }
    };
    auto flush = [&](int pos) {
        int gg  = pos >> 1, mtv = pos & 1;
        int cA0 = mtv * 96;
        float* po = out + (size_t)gg * NOUT;
        const int rA = lane >> 2, cB = (lane & 3) * 2;
#pragma unroll
        for (int i = 0; i < 3; i++) {
            int c0 = cA0 + wr * 48 + i * 16 + rA;
#pragma unroll
            for (int j = 0; j < 12; j++) {
                int d0 = wc * 96 + j * 8 + cB;
                atomicAdd(po + (size_t)c0 * C_ + d0,     acc[i][j][0]);
                atomicAdd(po + (size_t)c0 * C_ + d0 + 1, acc[i][j][1]);
                atomicAdd(po + (size_t)(c0 + 8) * C_ + d0,     acc[i][j][2]);
                atomicAdd(po + (size_t)(c0 + 8) * C_ + d0 + 1, acc[i][j][3]);
                acc[i][j][0] = 0.f; acc[i][j][1] = 0.f;
                acc[i][j][2] = 0.f; acc[i][j][3] = 0.f;
            }
        }
    };

    // ---- prologue ----
    fillB(0, r0);
    fillA(0, r0);
    cp_commit();

    // ---- persistent row loop ----
    for (int r = r0; r < r1; r++) {
        int st = (r - r0) & 1;
        __syncthreads();
        if (r + 1 < r1) {
            fillB(st ^ 1, r + 1);
            fillA(st ^ 1, r + 1);
            cp_commit();
            cp_wait<1>();
        } else {
            cp_wait<0>();
        }
        __syncthreads();

        uint32_t smA = smem + st * STAGE_B;
        uint32_t smB = smA + 12288;
        uint32_t aA0 = smA + (wr * 48 + mrel) * 128;
        uint32_t aB0 = smB + (wc * 96 + nrel) * 128;

#pragma unroll
        for (int ks = 0; ks < 4; ks++) {
            uint32_t af[3][4], bf[6][4];
#pragma unroll
            for (int i = 0; i < 3; i++)
                ldsm4(af[i], aA0 + i * (16 * 128) + (((ks * 2 + kcsA) ^ klane) << 4));
#pragma unroll
            for (int t = 0; t < 6; t++)
                ldsm4(bf[t], aB0 + t * (16 * 128) + (((ks * 2 + kcsB) ^ klane) << 4));
#pragma unroll
            for (int i = 0; i < 3; i++)
#pragma unroll
                for (int j = 0; j < 12; j++)
                    mma16(acc[i][j], af[i], &bf[j >> 1][(j & 1) * 2]);
        }

        if ((r & 63) == 63 || r == r1 - 1)
            flush(r >> 6);
    }
}

// ---------------------------------------------------------------------------
// fused norm: 8 blocks per g (grid 640, all resident -> spin barrier safe).
// ---------------------------------------------------------------------------
__global__ __launch_bounds__(256) void cofe_norm(float* __restrict__ out) {
    const int g = blockIdx.x >> 3, seg = blockIdx.x & 7;
    float4* p = reinterpret_cast<float4*>(out + (size_t)g * NOUT + seg * 4608);
    const int tid = threadIdx.x;

    float ss = 0.f;
#pragma unroll
    for (int i = tid; i < 1152; i += 256) {
        float4 v = p[i];
        ss += v.x * v.x + v.y * v.y + v.z * v.z + v.w * v.w;
    }
    __shared__ float red[8];
    __shared__ float s_scale;
#pragma unroll
    for (int d = 16; d > 0; d >>= 1) ss += __shfl_xor_sync(0xffffffffu, ss, d);
    if ((tid & 31) == 0) red[tid >> 5] = ss;
    __syncthreads();
    if (tid == 0) {
        float v = red[0] + red[1] + red[2] + red[3] +
                  red[4] + red[5] + red[6] + red[7];
        atomicAdd(&g_sums[g], v);
        __threadfence();
        atomicAdd(&g_cnt[g], 1);
        while (atomicAdd(&g_cnt[g], 0) < 8) { }
        __threadfence();
        float tot = atomicAdd(&g_sums[g], 0.0f);
        s_scale = 1.0f / fmaxf(sqrtf(tot), 1e-12f);
    }
    __syncthreads();
    const float scale = s_scale;

#pragma unroll
    for (int i = tid; i < 1152; i += 256) {
        float4 v = p[i];
        v.x *= scale; v.y *= scale; v.z *= scale; v.w *= scale;
        p[i] = v;
    }
}

// ---------------------------------------------------------------------------
extern "C" void kernel_launch(void* const* d_in, const int* in_sizes, int n_in,
                              void* d_out, int out_size) {
    const float* x = (const float*)d_in[0];
    float* out = (float*)d_out;

    int sms = 0;
    cudaDeviceGetAttribute(&sms, cudaDevAttrMultiProcessorCount, 0);
    if (sms <= 0) sms = 148;
    int grid = 2 * sms;

    cofe_prep<<<12288, 256>>>(x, out);
    cudaFuncSetAttribute(cofe_mma, cudaFuncAttributeMaxDynamicSharedMemorySize, SM_REQ);
    cofe_mma<<<grid, 128, SM_REQ>>>(out);
    cofe_norm<<<640, 256>>>(out);
}